// round 1
// baseline (speedup 1.0000x reference)
#include <cuda_runtime.h>

#define DIMN 32

__global__ __launch_bounds__(256) void poly_horner_kernel(
    const float* __restrict__ x,
    const float* __restrict__ w,
    float* __restrict__ out,
    int n_vec4)
{
    int i = blockIdx.x * blockDim.x + threadIdx.x;
    if (i >= n_vec4) return;

    // Load coefficients into registers (uniform across threads; L1/L2 broadcast)
    float wr[DIMN];
#pragma unroll
    for (int k = 0; k < DIMN; ++k) wr[k] = __ldg(&w[k]);

    float4 xv = reinterpret_cast<const float4*>(x)[i];

    float a0 = wr[DIMN - 1];
    float a1 = wr[DIMN - 1];
    float a2 = wr[DIMN - 1];
    float a3 = wr[DIMN - 1];

#pragma unroll
    for (int k = DIMN - 2; k >= 0; --k) {
        a0 = fmaf(a0, xv.x, wr[k]);
        a1 = fmaf(a1, xv.y, wr[k]);
        a2 = fmaf(a2, xv.z, wr[k]);
        a3 = fmaf(a3, xv.w, wr[k]);
    }

    float4 ov;
    ov.x = a0; ov.y = a1; ov.z = a2; ov.w = a3;
    reinterpret_cast<float4*>(out)[i] = ov;
}

extern "C" void kernel_launch(void* const* d_in, const int* in_sizes, int n_in,
                              void* d_out, int out_size) {
    const float* x = (const float*)d_in[0];
    const float* w = (const float*)d_in[1];
    float* out = (float*)d_out;

    int n = in_sizes[0];          // 4194304, divisible by 4
    int n_vec4 = n / 4;           // 1048576
    int threads = 256;
    int blocks = (n_vec4 + threads - 1) / threads;

    poly_horner_kernel<<<blocks, threads>>>(x, w, out, n_vec4);
}

// round 2
// speedup vs baseline: 1.1899x; 1.1899x over previous
#include <cuda_runtime.h>

#define DIMN 32

// 64-bit packed f32x2 helpers (Blackwell packed-FP32 pipe, PTX-only)
__device__ __forceinline__ unsigned long long pack2(float lo, float hi) {
    unsigned long long r;
    asm("mov.b64 %0, {%1, %2};" : "=l"(r) : "f"(lo), "f"(hi));
    return r;
}
__device__ __forceinline__ void unpack2(unsigned long long v, float& lo, float& hi) {
    asm("mov.b64 {%0, %1}, %2;" : "=f"(lo), "=f"(hi) : "l"(v));
}
__device__ __forceinline__ unsigned long long fma2(unsigned long long a,
                                                   unsigned long long b,
                                                   unsigned long long c) {
    unsigned long long d;
    asm("fma.rn.f32x2 %0, %1, %2, %3;" : "=l"(d) : "l"(a), "l"(b), "l"(c));
    return d;
}

__global__ __launch_bounds__(256, 2) void poly_horner_f32x2_kernel(
    const float* __restrict__ x,
    const float* __restrict__ w,
    float* __restrict__ out,
    int n_vec8)
{
    int i = blockIdx.x * blockDim.x + threadIdx.x;
    if (i >= n_vec8) return;

    // Pack coefficients as (w_k, w_k) pairs once per thread (L1/L2 broadcast loads)
    unsigned long long wp[DIMN];
#pragma unroll
    for (int k = 0; k < DIMN; ++k) {
        float wk = __ldg(&w[k]);
        wp[k] = pack2(wk, wk);
    }

    // 8 elements per thread = two float4 loads = 4 independent f32x2 Horner chains
    const float4* x4 = reinterpret_cast<const float4*>(x);
    float4 xa = x4[2 * i + 0];
    float4 xb = x4[2 * i + 1];

    unsigned long long p0 = pack2(xa.x, xa.y);
    unsigned long long p1 = pack2(xa.z, xa.w);
    unsigned long long p2 = pack2(xb.x, xb.y);
    unsigned long long p3 = pack2(xb.z, xb.w);

    unsigned long long a0 = wp[DIMN - 1];
    unsigned long long a1 = wp[DIMN - 1];
    unsigned long long a2 = wp[DIMN - 1];
    unsigned long long a3 = wp[DIMN - 1];

#pragma unroll
    for (int k = DIMN - 2; k >= 0; --k) {
        a0 = fma2(a0, p0, wp[k]);
        a1 = fma2(a1, p1, wp[k]);
        a2 = fma2(a2, p2, wp[k]);
        a3 = fma2(a3, p3, wp[k]);
    }

    float4 oa, ob;
    unpack2(a0, oa.x, oa.y);
    unpack2(a1, oa.z, oa.w);
    unpack2(a2, ob.x, ob.y);
    unpack2(a3, ob.z, ob.w);

    float4* o4 = reinterpret_cast<float4*>(out);
    o4[2 * i + 0] = oa;
    o4[2 * i + 1] = ob;
}

extern "C" void kernel_launch(void* const* d_in, const int* in_sizes, int n_in,
                              void* d_out, int out_size) {
    const float* x = (const float*)d_in[0];
    const float* w = (const float*)d_in[1];
    float* out = (float*)d_out;

    int n = in_sizes[0];          // 4194304, divisible by 8
    int n_vec8 = n / 8;           // 524288
    int threads = 256;
    int blocks = (n_vec8 + threads - 1) / threads;

    poly_horner_f32x2_kernel<<<blocks, threads>>>(x, w, out, n_vec8);
}

// round 3
// speedup vs baseline: 1.2240x; 1.0286x over previous
#include <cuda_runtime.h>

#define DIMN 32
#define TPB 256
#define CHAINS 8   // 8 f32x2 chains = 16 elements per thread

__device__ unsigned long long g_wp[DIMN];

__device__ __forceinline__ unsigned long long pack2(float lo, float hi) {
    unsigned long long r;
    asm("mov.b64 %0, {%1, %2};" : "=l"(r) : "f"(lo), "f"(hi));
    return r;
}
__device__ __forceinline__ void unpack2(unsigned long long v, float& lo, float& hi) {
    asm("mov.b64 {%0, %1}, %2;" : "=f"(lo), "=f"(hi) : "l"(v));
}
__device__ __forceinline__ unsigned long long fma2(unsigned long long a,
                                                   unsigned long long b,
                                                   unsigned long long c) {
    unsigned long long d;
    asm("fma.rn.f32x2 %0, %1, %2, %3;" : "=l"(d) : "l"(a), "l"(b), "l"(c));
    return d;
}

// Pre-pack (w_k, w_k) pairs once; runs before the main kernel on the same stream.
__global__ void pack_w_kernel(const float* __restrict__ w) {
    int k = threadIdx.x;
    if (k < DIMN) {
        float wk = w[k];
        g_wp[k] = pack2(wk, wk);
    }
}

__global__ __launch_bounds__(TPB) void poly_horner8_kernel(
    const float* __restrict__ x,
    float* __restrict__ out,
    int n_vec4)
{
    // Block-contiguous mapping: block owns TPB*4 consecutive float4s,
    // each thread takes 4 of them strided by TPB -> fully coalesced.
    int base4 = blockIdx.x * (TPB * 4) + threadIdx.x;

    // ---- coefficients: load all 32 packed pairs up front, then pin ----
    unsigned long long wp[DIMN];
#pragma unroll
    for (int k = 0; k < DIMN; ++k) wp[k] = g_wp[k];
#pragma unroll
    for (int k = 0; k < DIMN; ++k) asm volatile("" : "+l"(wp[k]));

    // ---- load 4 float4 = 16 elements ----
    const float4* x4 = reinterpret_cast<const float4*>(x);
    float4 xv[4];
#pragma unroll
    for (int j = 0; j < 4; ++j) {
        int idx = base4 + j * TPB;
        if (idx < n_vec4) xv[j] = x4[idx];
        else xv[j] = make_float4(0.f, 0.f, 0.f, 0.f);
    }

    unsigned long long p[CHAINS];
#pragma unroll
    for (int j = 0; j < 4; ++j) {
        p[2 * j + 0] = pack2(xv[j].x, xv[j].y);
        p[2 * j + 1] = pack2(xv[j].z, xv[j].w);
    }

    unsigned long long a[CHAINS];
#pragma unroll
    for (int c = 0; c < CHAINS; ++c) a[c] = wp[DIMN - 1];

    // ---- pure FFMA2 Horner: 31 steps x 8 independent chains ----
#pragma unroll
    for (int k = DIMN - 2; k >= 0; --k) {
#pragma unroll
        for (int c = 0; c < CHAINS; ++c) {
            a[c] = fma2(a[c], p[c], wp[k]);
        }
    }

    // ---- store 4 float4 ----
    float4* o4 = reinterpret_cast<float4*>(out);
#pragma unroll
    for (int j = 0; j < 4; ++j) {
        int idx = base4 + j * TPB;
        if (idx < n_vec4) {
            float4 ov;
            unpack2(a[2 * j + 0], ov.x, ov.y);
            unpack2(a[2 * j + 1], ov.z, ov.w);
            o4[idx] = ov;
        }
    }
}

extern "C" void kernel_launch(void* const* d_in, const int* in_sizes, int n_in,
                              void* d_out, int out_size) {
    const float* x = (const float*)d_in[0];
    const float* w = (const float*)d_in[1];
    float* out = (float*)d_out;

    int n = in_sizes[0];            // 4194304
    int n_vec4 = n / 4;             // 1048576 float4s
    int blocks = (n_vec4 + TPB * 4 - 1) / (TPB * 4);  // 1024

    pack_w_kernel<<<1, DIMN>>>(w);
    poly_horner8_kernel<<<blocks, TPB>>>(x, out, n_vec4);
}